// round 16
// baseline (speedup 1.0000x reference)
#include <cuda_runtime.h>
#include <cuda_bf16.h>
#include <cstdint>
#include <cstddef>

#define DEV __device__ __forceinline__

// ---------------- problem dims ----------------
#define DDIM 1024
#define HDIM 4096
#define MM   16384
#define N1  ((long long)MM * DDIM)        // 16,777,216
#define N2  ((long long)MM * HDIM)        // 67,108,864
#define NW1 ((long long)HDIM * DDIM)      // 4,194,304
#define NW2 ((long long)DDIM * HDIM)      // 4,194,304
#define RANK1 16693329LL                  // nearest-rank 0.995 quantile over N1

// ---------------- device scratch ----------------
__device__ float          g_h1 [(size_t)N1];     // LN output fp32
__device__ __nv_bfloat16  g_h1q[(size_t)N1];     // bf16 acts layer1 (exact ints)
__device__ short          g_n2 [(size_t)N2];     // GEMM1 integer output (exact)
__device__ __nv_bfloat16  g_a2q[(size_t)N2];     // bf16 acts layer2 (exact ints)
__device__ __nv_bfloat16  g_w1q[(size_t)NW1];    // ternary w1
__device__ __nv_bfloat16  g_w2q[(size_t)NW2];    // ternary w2
__device__ unsigned       g_hist2[65536];        // hist of n; re-zeroed in GEMM2 prologue
__device__ unsigned short g_lut[65536];          // n -> quantized gelu (bf16 bits)

__device__ unsigned  g_bins[2048];               // level-0 radix bins (self-rezeroing)
__device__ unsigned  g_bins21[1 << 21];          // low-21-bit histogram (zeroed in GEMM1 prologue)
__device__ unsigned  g_chunk[2048];              // chunk sums (self-rezeroing)
__device__ unsigned  g_prefix;
__device__ long long g_rank;
__device__ float     g_s[2];        // s = 127/amax
__device__ float     g_gamma[2];    // gamma = mean|w| + 1e-5
__device__ float     g_sc1;         // gamma1/s1
__device__ double    g_wpart[2][1024];
__device__ unsigned  g_ctr[8];      // last-block counters (self-resetting)

// ---------------- helpers ----------------
DEV float ff_warp_sum(float v) {
    #pragma unroll
    for (int o = 16; o; o >>= 1) v += __shfl_xor_sync(0xffffffffu, v, o);
    return v;
}
DEV float ff_gelu(float x) {
    return 0.5f * x * (1.0f + erff(x * 0.70710678118654752440f));
}
DEV unsigned ff_pack_bf16(float a, float b) {
    __nv_bfloat162 p = __floats2bfloat162_rn(a, b);
    return *reinterpret_cast<unsigned*>(&p);
}
DEV void ff_cp_async16(void* sdst, const void* gsrc) {
    unsigned d = (unsigned)__cvta_generic_to_shared(sdst);
    asm volatile("cp.async.cg.shared.global [%0], [%1], 16;\n" :: "r"(d), "l"(gsrc));
}
DEV bool ff_last_block_n(int slot, unsigned total) {
    __shared__ bool isLast;
    if (threadIdx.x == 0) {
        __threadfence();
        unsigned v = atomicAdd(&g_ctr[slot], 1u);
        isLast = (v == total - 1);
    }
    __syncthreads();
    return isLast;
}

// parallel bin-select over bins[0..nbins) with 256 threads; nbins multiple of 256
DEV void ff_pselect(const unsigned* bins, int nbins, long long r,
                    int* sel_out, long long* rem_out) {
    __shared__ long long spre[256];
    __shared__ int s_sel;
    __shared__ long long s_rem;
    int t = threadIdx.x;
    int per = nbins >> 8;
    unsigned mysum = 0;
    for (int j = 0; j < per; j++) mysum += bins[t * per + j];
    spre[t] = (long long)mysum;
    __syncthreads();
    #pragma unroll
    for (int off = 1; off < 256; off <<= 1) {
        long long add = (t >= off) ? spre[t - off] : 0;
        __syncthreads();
        spre[t] += add;
        __syncthreads();
    }
    long long incl = spre[t];
    long long excl = incl - (long long)mysum;
    if (r >= excl && r < incl) {
        long long rr = r - excl;
        for (int j = 0; j < per; j++) {
            unsigned c = bins[t * per + j];
            if (rr < (long long)c) { s_sel = t * per + j; s_rem = rr; break; }
            rr -= (long long)c;
        }
    }
    __syncthreads();
    *sel_out = s_sel;
    *rem_out = s_rem;
}

// ---------------- layernorm (one-pass reduction) + fused level-0 histogram ----------------
__global__ __launch_bounds__(256) void ff_ln_kernel(
    const float* __restrict__ x, const float* __restrict__ gam,
    const float* __restrict__ bet)
{
    int row = blockIdx.x;
    int tid = threadIdx.x, w = tid >> 5, l = tid & 31;

    __shared__ unsigned sb[2048];
    for (int i = tid; i < 2048; i += 256) sb[i] = 0u;

    const float4* xr = (const float4*)(x + (size_t)row * DDIM);
    float4 v = xr[tid];

    __shared__ float sh[8], sh2[8];
    __shared__ float s_mu, s_inv;

    // one pass: sum and sum of squares
    float s  = v.x + v.y + v.z + v.w;
    float ss = v.x*v.x + v.y*v.y + v.z*v.z + v.w*v.w;
    float ws  = ff_warp_sum(s);
    float wss = ff_warp_sum(ss);
    if (l == 0) { sh[w] = ws; sh2[w] = wss; }
    __syncthreads();
    if (w == 0) {
        float a = (l < 8) ? sh[l]  : 0.0f;
        float b = (l < 8) ? sh2[l] : 0.0f;
        a = ff_warp_sum(a);
        b = ff_warp_sum(b);
        if (l == 0) {
            float mu = a * (1.0f / DDIM);
            s_mu  = mu;
            s_inv = rsqrtf(b * (1.0f / DDIM) - mu * mu + 1e-5f);
        }
    }
    __syncthreads();
    float mu = s_mu, inv = s_inv;

    float dx = v.x - mu, dy = v.y - mu, dz = v.z - mu, dw = v.w - mu;
    float4 g4 = ((const float4*)gam)[tid], b4 = ((const float4*)bet)[tid];
    float4 o;
    o.x = dx * inv * g4.x + b4.x;
    o.y = dy * inv * g4.y + b4.y;
    o.z = dz * inv * g4.z + b4.z;
    o.w = dw * inv * g4.w + b4.w;
    ((float4*)(g_h1 + (size_t)row * DDIM))[tid] = o;

    atomicAdd(&sb[__float_as_uint(fabsf(o.x)) >> 21], 1u);
    atomicAdd(&sb[__float_as_uint(fabsf(o.y)) >> 21], 1u);
    atomicAdd(&sb[__float_as_uint(fabsf(o.z)) >> 21], 1u);
    atomicAdd(&sb[__float_as_uint(fabsf(o.w)) >> 21], 1u);
    __syncthreads();
    for (int i = tid; i < 2048; i += 256)
        if (sb[i]) atomicAdd(&g_bins[i], sb[i]);
}

// ---------------- both weights: mean|w| + gamma; global last block runs level-0 scan ----------------
__global__ __launch_bounds__(256) void ff_wabs2(const float* __restrict__ w1,
                                                const float* __restrict__ w2)
{
    int half = blockIdx.x >> 10;
    int blk  = blockIdx.x & 1023;
    const float4* p = (const float4*)(half ? w2 : w1) + (size_t)blk * 1024;

    float acc = 0.0f;
    #pragma unroll
    for (int i = 0; i < 4; i++) {
        float4 v = p[threadIdx.x + i * 256];
        acc += fabsf(v.x) + fabsf(v.y) + fabsf(v.z) + fabsf(v.w);
    }
    float ws = ff_warp_sum(acc);
    __shared__ float sw[8];
    int wid = threadIdx.x >> 5, l = threadIdx.x & 31;
    if (l == 0) sw[wid] = ws;
    __syncthreads();
    if (threadIdx.x == 0) {
        double b = 0.0;
        for (int i = 0; i < 8; i++) b += (double)sw[i];
        g_wpart[half][blk] = b;
    }

    if (ff_last_block_n(half, 1024)) {
        if (threadIdx.x == 0) {
            double t = 0.0;
            for (int i = 0; i < 1024; i++) t += g_wpart[half][i];
            g_gamma[half] = (float)(t / (double)NW1) + 1e-5f;
            g_ctr[half] = 0u;
        }
    }

    if (ff_last_block_n(4, 2048)) {
        int sel; long long rem;
        ff_pselect(g_bins, 2048, RANK1, &sel, &rem);
        if (threadIdx.x == 0) {
            g_prefix = (unsigned)sel << 21;
            g_rank   = rem;
            g_ctr[4] = 0u;
        }
        __syncthreads();
        for (int i = threadIdx.x; i < 2048; i += 256) g_bins[i] = 0u;
    }
}

// ---------------- both weights: ternary quantize (bf16) ----------------
__global__ __launch_bounds__(256) void ff_wquant2(const float* __restrict__ w1,
                                                  const float* __restrict__ w2)
{
    int half = blockIdx.x >> 11;
    int blk  = blockIdx.x & 2047;
    float g = g_gamma[half];
    const float4* p = (const float4*)(half ? w2 : w1);
    __nv_bfloat16* out = half ? g_w2q : g_w1q;
    long long n4 = NW1 / 4;
    long long stride = 2048LL * 256;
    for (long long i = (long long)blk * 256 + threadIdx.x; i < n4; i += stride) {
        float4 v = p[i];
        float t0 = fminf(fmaxf(rintf(v.x / g), -1.0f), 1.0f);
        float t1 = fminf(fmaxf(rintf(v.y / g), -1.0f), 1.0f);
        float t2 = fminf(fmaxf(rintf(v.z / g), -1.0f), 1.0f);
        float t3 = fminf(fmaxf(rintf(v.w / g), -1.0f), 1.0f);
        uint2 o;
        o.x = ff_pack_bf16(t0, t1);
        o.y = ff_pack_bf16(t2, t3);
        ((uint2*)out)[i] = o;
    }
}

// ---------------- 21-bit histogram + fused hierarchical select (grid-last block) ----------------
__global__ __launch_bounds__(256) void ff_hist21(long long n4) {
    unsigned pref = g_prefix;              // sel0 << 21
    const float4* p = (const float4*)(const float*)g_h1;
    long long stride = (long long)gridDim.x * blockDim.x;
    long long base = (long long)blockIdx.x * blockDim.x + threadIdx.x;
    for (long long i = base; i < n4; i += 2 * stride) {
        float4 v0 = p[i];
        bool has2 = (i + stride) < n4;
        float4 v1 = has2 ? p[i + stride] : make_float4(-1.f, -1.f, -1.f, -1.f);
        float vv[8] = {v0.x, v0.y, v0.z, v0.w, v1.x, v1.y, v1.z, v1.w};
        int cnt = has2 ? 8 : 4;
        #pragma unroll
        for (int j = 0; j < 8; j++) {
            if (j >= cnt) break;
            unsigned u = __float_as_uint(fabsf(vv[j]));
            if ((u & 0xFFE00000u) == pref) {
                unsigned low = u & 0x1FFFFFu;
                atomicAdd(&g_bins21[low], 1u);
                atomicAdd(&g_chunk[low >> 10], 1u);
            }
        }
    }

    if (ff_last_block_n(5, gridDim.x)) {
        int c; long long rr;
        ff_pselect(g_chunk, 2048, g_rank, &c, &rr);
        int b; long long dummy;
        ff_pselect(g_bins21 + (size_t)c * 1024, 1024, rr, &b, &dummy);
        if (threadIdx.x == 0) {
            unsigned bits = g_prefix | (unsigned)(c * 1024 + b);
            float amax = fmaxf(__uint_as_float(bits), 1e-5f);
            g_s[0] = 127.0f / amax;
            g_ctr[5] = 0u;
        }
        __syncthreads();
        for (int i = threadIdx.x; i < 2048; i += 256) g_chunk[i] = 0u;
    }
}

// ---------------- layer-1 activation quantize -> bf16 ints (2x ILP) ----------------
__global__ __launch_bounds__(256) void ff_actquant1(long long n4) {
    float s = g_s[0];
    const float4* in = (const float4*)(const float*)g_h1;
    uint2* out = (uint2*)g_h1q;
    long long stride = (long long)gridDim.x * blockDim.x;
    long long base = (long long)blockIdx.x * blockDim.x + threadIdx.x;
    for (long long i = base; i < n4; i += 2 * stride) {
        float4 v = in[i];
        uint2 o;
        o.x = ff_pack_bf16(fminf(fmaxf(rintf(v.x * s), -128.0f), 127.0f),
                           fminf(fmaxf(rintf(v.y * s), -128.0f), 127.0f));
        o.y = ff_pack_bf16(fminf(fmaxf(rintf(v.z * s), -128.0f), 127.0f),
                           fminf(fmaxf(rintf(v.w * s), -128.0f), 127.0f));
        out[i] = o;
        if (i + stride < n4) {
            float4 u = in[i + stride];
            uint2 o2;
            o2.x = ff_pack_bf16(fminf(fmaxf(rintf(u.x * s), -128.0f), 127.0f),
                                fminf(fmaxf(rintf(u.y * s), -128.0f), 127.0f));
            o2.y = ff_pack_bf16(fminf(fmaxf(rintf(u.z * s), -128.0f), 127.0f),
                                fminf(fmaxf(rintf(u.w * s), -128.0f), 127.0f));
            out[i + stride] = o2;
        }
    }
}

// ---------------- bf16 GEMM: 128x128 tile, K=64/stage, 3 stages, 2 CTA/SM ----------------
// GEMM1 prologue re-zeros g_bins21; GEMM2 prologue re-zeros g_hist2 (both hidden
// under cp.async). GEMM1 epilogue fuses layer-2 histogram + quantile scan.
#define GSTG 32768                 // A 16KB + B 16KB per stage
#define GSMEM (3 * GSTG)           // 96KB dynamic

DEV void ff_load_stage(const __nv_bfloat16* A, const __nv_bfloat16* Bw, int K,
                       int bm, int bn, int kt, unsigned char* sa, int tid)
{
    unsigned char* sb = sa + 16384;
    #pragma unroll
    for (int i = 0; i < 4; i++) {
        int id = tid + i * 256;           // 0..1023
        int row = id >> 3, ch = id & 7;
        int sw = ch ^ (row & 7);
        ff_cp_async16(sa + (row * 8 + sw) * 16, A  + (size_t)(bm + row) * K + kt * 64 + ch * 8);
        ff_cp_async16(sb + (row * 8 + sw) * 16, Bw + (size_t)(bn + row) * K + kt * 64 + ch * 8);
    }
    asm volatile("cp.async.commit_group;\n");
}

template<int LAYER>
__global__ __launch_bounds__(256, 2) void ff_gemm(float* __restrict__ Cext)
{
    constexpr int KD = LAYER ? HDIM : DDIM;
    constexpr int ND = LAYER ? DDIM : HDIM;
    constexpr int KT = KD >> 6;          // K=64 per stage
    const __nv_bfloat16* A  = LAYER ? g_a2q : g_h1q;
    const __nv_bfloat16* Bw = LAYER ? g_w2q : g_w1q;

    extern __shared__ __align__(128) unsigned char smem[];
    const int tid  = threadIdx.x;
    const int lane = tid & 31, warp = tid >> 5;
    const int wm = warp >> 2, wn = warp & 3;     // 2 x 4 warp grid
    const int bm = blockIdx.y * 128, bn = blockIdx.x * 128;   // N on x (L2 reuse)

    float acc[4][4][4];
    #pragma unroll
    for (int a = 0; a < 4; a++)
        #pragma unroll
        for (int b = 0; b < 4; b++)
            #pragma unroll
            for (int c = 0; c < 4; c++) acc[a][b][c] = 0.0f;

    ff_load_stage(A, Bw, KD, bm, bn, 0, smem + 0 * GSTG, tid);
    ff_load_stage(A, Bw, KD, bm, bn, 1, smem + 1 * GSTG, tid);

    if (LAYER == 0) {
        // hidden under the async loads: re-zero g_bins21 for the next replay
        size_t bid = (size_t)blockIdx.y * gridDim.x + blockIdx.x;   // 0..4095
        size_t b0 = bid * 512;
        g_bins21[b0 + tid] = 0u;
        g_bins21[b0 + 256 + tid] = 0u;
    } else {
        // hidden under the async loads: re-zero g_hist2 for the next replay
        size_t bid = (size_t)blockIdx.y * gridDim.x + blockIdx.x;   // 0..1023
        if (tid < 64) g_hist2[bid * 64 + tid] = 0u;
    }

    for (int kt = 0; kt < KT; kt++) {
        if (kt < KT - 1) asm volatile("cp.async.wait_group 1;\n" ::: "memory");
        else             asm volatile("cp.async.wait_group 0;\n" ::: "memory");
        __syncthreads();
        if (kt + 2 < KT)
            ff_load_stage(A, Bw, KD, bm, bn, kt + 2, smem + ((kt + 2) % 3) * GSTG, tid);

        unsigned char* sa = smem + (kt % 3) * GSTG;
        unsigned char* sb = sa + 16384;

        #pragma unroll
        for (int s = 0; s < 4; s++) {             // four k16 steps per K=64 stage
            unsigned ar[4][4];
            #pragma unroll
            for (int mi = 0; mi < 4; mi++) {
                int row = wm * 64 + mi * 16 + ((lane >> 3) & 1) * 8 + (lane & 7);
                int ch  = (2 * s + (lane >> 4)) ^ (row & 7);
                unsigned addr = (unsigned)__cvta_generic_to_shared(sa + (row * 8 + ch) * 16);
                asm volatile("ldmatrix.sync.aligned.m8n8.x4.shared.b16 {%0,%1,%2,%3}, [%4];\n"
                    : "=r"(ar[mi][0]), "=r"(ar[mi][1]), "=r"(ar[mi][2]), "=r"(ar[mi][3])
                    : "r"(addr));
            }
            unsigned br[4][2];
            #pragma unroll
            for (int nj2 = 0; nj2 < 2; nj2++) {
                int row = wn * 32 + nj2 * 16 + ((lane >> 3) & 1) * 8 + (lane & 7);
                int ch  = (2 * s + (lane >> 4)) ^ (row & 7);
                unsigned addr = (unsigned)__cvta_generic_to_shared(sb + (row * 8 + ch) * 16);
                unsigned q0, q1, q2, q3;
                asm volatile("ldmatrix.sync.aligned.m8n8.x4.shared.b16 {%0,%1,%2,%3}, [%4];\n"
                    : "=r"(q0), "=r"(q1), "=r"(q2), "=r"(q3) : "r"(addr));
                br[2 * nj2][0] = q0;     br[2 * nj2][1] = q2;
                br[2 * nj2 + 1][0] = q1; br[2 * nj2 + 1][1] = q3;
            }
            #pragma unroll
            for (int mi = 0; mi < 4; mi++)
                #pragma unroll
                for (int nj = 0; nj < 4; nj++) {
                    asm volatile(
                        "mma.sync.aligned.m16n8k16.row.col.f32.bf16.bf16.f32 "
                        "{%0,%1,%2,%3},{%4,%5,%6,%7},{%8,%9},{%0,%1,%2,%3};\n"
                        : "+f"(acc[mi][nj][0]), "+f"(acc[mi][nj][1]),
                          "+f"(acc[mi][nj][2]), "+f"(acc[mi][nj][3])
                        : "r"(ar[mi][0]), "r"(ar[mi][1]), "r"(ar[mi][2]), "r"(ar[mi][3]),
                          "r"(br[nj][0]), "r"(br[nj][1]));
                }
        }
    }

    if (LAYER == 0) {
        __syncthreads();
        unsigned* hb = (unsigned*)smem;
        for (int i = tid; i < 8192; i += 256) hb[i] = 0u;
        __syncthreads();

        #pragma unroll
        for (int mi = 0; mi < 4; mi++) {
            int r0 = bm + wm * 64 + mi * 16 + (lane >> 2);
            #pragma unroll
            for (int nj = 0; nj < 4; nj++) {
                int cc = bn + wn * 32 + nj * 8 + (lane & 3) * 2;
                int c0 = min(max((int)acc[mi][nj][0], -32768), 32767);
                int c1 = min(max((int)acc[mi][nj][1], -32768), 32767);
                int c2 = min(max((int)acc[mi][nj][2], -32768), 32767);
                int c3 = min(max((int)acc[mi][nj][3], -32768), 32767);
                int b0 = c0 + 4096, b1 = c1 + 4096, b2 = c2 + 4096, b3 = c3 + 4096;
                if ((unsigned)b0 < 8192u) atomicAdd(&hb[b0], 1u); else atomicAdd(&g_hist2[c0 + 32768], 1u);
                if ((unsigned)b1 < 8192u) atomicAdd(&hb[b1], 1u); else atomicAdd(&g_hist2[c1 + 32768], 1u);
                if ((unsigned)b2 < 8192u) atomicAdd(&hb[b2], 1u); else atomicAdd(&g_hist2[c2 + 32768], 1u);
                if ((unsigned)b3 < 8192u) atomicAdd(&hb[b3], 1u); else atomicAdd(&g_hist2[c3 + 32768], 1u);
                *(unsigned*)(g_n2 + (size_t)r0 * ND + cc) =
                    ((unsigned)(unsigned short)(short)c0) | (((unsigned)(unsigned short)(short)c1) << 16);
                *(unsigned*)(g_n2 + (size_t)(r0 + 8) * ND + cc) =
                    ((unsigned)(unsigned short)(short)c2) | (((unsigned)(unsigned short)(short)c3) << 16);
            }
        }
        __syncthreads();
        for (int i = tid; i < 8192; i += 256)
            if (hb[i]) atomicAdd(&g_hist2[i + (32768 - 4096)], hb[i]);

        if (ff_last_block_n(3, gridDim.x * gridDim.y)) {
            long long* partial = (long long*)(smem + 32768);
            int t = tid;
            long long c = 0;
            for (int b = t * 256; b < (t + 1) * 256; b++) c += (long long)g_hist2[b];
            partial[t] = c;
            __syncthreads();
            if (t == 0) {
                double idx = 0.995 * (double)(N2 - 1);
                long long k = (long long)idx;
                double f = idx - (double)k;
                long long cum = 0;
                int chunk = 0;
                for (; chunk < 256; chunk++) {
                    if (cum + partial[chunk] > k) break;
                    cum += partial[chunk];
                }
                long long r = k - cum;
                int nk = 0, nk1 = 0;
                int b = chunk * 256;
                for (;; b++) {
                    long long cc2 = (long long)g_hist2[b];
                    if (r < cc2) {
                        nk = b - 32768;
                        if (r + 1 < cc2) nk1 = nk;
                        else {
                            int b2 = b + 1;
                            while (b2 < 65536 && g_hist2[b2] == 0u) b2++;
                            nk1 = (b2 < 65536) ? (b2 - 32768) : nk;
                        }
                        break;
                    }
                    r -= cc2;
                }
                float sc1 = g_gamma[0] / g_s[0];
                float v0 = ff_gelu(sc1 * (float)nk);
                float v1 = ff_gelu(sc1 * (float)nk1);
                float amax = fmaxf((float)((1.0 - f) * (double)v0 + f * (double)v1), 1e-5f);
                g_s[1] = 127.0f / amax;
                g_sc1 = sc1;
                g_ctr[3] = 0u;
            }
        }
    } else {
        float sc = g_gamma[1] / g_s[1];
        #pragma unroll
        for (int mi = 0; mi < 4; mi++) {
            int r0 = bm + wm * 64 + mi * 16 + (lane >> 2);
            #pragma unroll
            for (int nj = 0; nj < 4; nj++) {
                int cc = bn + wn * 32 + nj * 8 + (lane & 3) * 2;
                float2 p0 = make_float2(acc[mi][nj][0] * sc, acc[mi][nj][1] * sc);
                float2 p1 = make_float2(acc[mi][nj][2] * sc, acc[mi][nj][3] * sc);
                *(float2*)(Cext + (size_t)r0 * ND + cc) = p0;
                *(float2*)(Cext + (size_t)(r0 + 8) * ND + cc) = p1;
            }
        }
    }
}

// ---------------- LUT build ----------------
__global__ void ff_lut_build() {
    int i = blockIdx.x * blockDim.x + threadIdx.x;   // 65536
    int n = i - 32768;
    float g = ff_gelu(g_sc1 * (float)n);
    float q = fminf(fmaxf(rintf(g * g_s[1]), -128.0f), 127.0f);
    __nv_bfloat16 b = __float2bfloat16(q);
    g_lut[i] = *reinterpret_cast<unsigned short*>(&b);
}

// ---------------- layer-2 quantize via LUT gather -> bf16 (2x ILP) ----------------
__global__ __launch_bounds__(256) void ff_actquant2(long long n8) {
    const uint4* in = (const uint4*)g_n2;
    uint4* out = (uint4*)g_a2q;
    const unsigned short* lut = g_lut;
    long long stride = (long long)gridDim.x * blockDim.x;
    long long base = (long long)blockIdx.x * blockDim.x + threadIdx.x;
    for (long long i = base; i < n8; i += 2 * stride) {
        uint4 v0 = in[i];
        unsigned o0[4];
        #pragma unroll
        for (int j = 0; j < 4; j++) {
            unsigned wj = (&v0.x)[j];
            unsigned lo = lut[(wj & 0xffffu) ^ 0x8000u];
            unsigned hi = lut[(wj >> 16) ^ 0x8000u];
            o0[j] = lo | (hi << 16);
        }
        out[i] = make_uint4(o0[0], o0[1], o0[2], o0[3]);
        if (i + stride < n8) {
            uint4 v1 = in[i + stride];
            unsigned o1[4];
            #pragma unroll
            for (int j = 0; j < 4; j++) {
                unsigned wj = (&v1.x)[j];
                unsigned lo = lut[(wj & 0xffffu) ^ 0x8000u];
                unsigned hi = lut[(wj >> 16) ^ 0x8000u];
                o1[j] = lo | (hi << 16);
            }
            out[i + stride] = make_uint4(o1[0], o1[1], o1[2], o1[3]);
        }
    }
}

// ---------------- launch ----------------
extern "C" void kernel_launch(void* const* d_in, const int* in_sizes, int n_in,
                              void* d_out, int out_size)
{
    const float* x    = (const float*)d_in[0];
    const float* ln_g = (const float*)d_in[1];
    const float* ln_b = (const float*)d_in[2];
    const float* w1   = (const float*)d_in[3];
    const float* w2   = (const float*)d_in[4];
    float* out = (float*)d_out;

    cudaFuncSetAttribute(ff_gemm<0>, cudaFuncAttributeMaxDynamicSharedMemorySize, GSMEM);
    cudaFuncSetAttribute(ff_gemm<1>, cudaFuncAttributeMaxDynamicSharedMemorySize, GSMEM);

    // LayerNorm (one-pass reduction, fused level-0 histogram)
    ff_ln_kernel<<<MM, 256>>>(x, ln_g, ln_b);

    // Weight gammas (+ fused level-0 scan in global last block), then quantize
    ff_wabs2<<<2048, 256>>>(w1, w2);
    ff_wquant2<<<4096, 256>>>(w1, w2);

    // Layer-1 quantile: 21-bit histogram with fused hierarchical select
    ff_hist21<<<2048, 256>>>(N1 / 4);

    // Quantize acts #1 -> bf16 ints
    ff_actquant1<<<4096, 256>>>(N1 / 4);

    // GEMM1 (prologue rezeros bins21; epilogue: layer-2 histogram + quantile)
    ff_gemm<0><<<dim3(HDIM / 128, MM / 128), 256, GSMEM>>>(nullptr);

    // LUT build
    ff_lut_build<<<256, 256>>>();

    // GELU + quantize acts #2 via LUT -> bf16 ints
    ff_actquant2<<<8192, 256>>>(N2 / 8);

    // GEMM2 (prologue rezeros hist2) -> fp32 output
    ff_gemm<1><<<dim3(DDIM / 128, MM / 128), 256, GSMEM>>>(out);
}

// round 17
// speedup vs baseline: 1.0140x; 1.0140x over previous
#include <cuda_runtime.h>
#include <cuda_bf16.h>
#include <cstdint>
#include <cstddef>

#define DEV __device__ __forceinline__

// ---------------- problem dims ----------------
#define DDIM 1024
#define HDIM 4096
#define MM   16384
#define N1  ((long long)MM * DDIM)        // 16,777,216
#define N2  ((long long)MM * HDIM)        // 67,108,864
#define NW1 ((long long)HDIM * DDIM)      // 4,194,304
#define NW2 ((long long)DDIM * HDIM)      // 4,194,304
#define RANK1 16693329LL                  // nearest-rank 0.995 quantile over N1

// ---------------- device scratch ----------------
__device__ float          g_h1 [(size_t)N1];     // LN output fp32
__device__ __nv_bfloat16  g_h1q[(size_t)N1];     // bf16 acts layer1 (exact ints)
__device__ short          g_n2 [(size_t)N2];     // GEMM1 integer output (exact)
__device__ __nv_bfloat16  g_a2q[(size_t)N2];     // bf16 acts layer2 (exact ints)
__device__ __nv_bfloat16  g_w1q[(size_t)NW1];    // ternary w1
__device__ __nv_bfloat16  g_w2q[(size_t)NW2];    // ternary w2
__device__ unsigned       g_hist2[65536];        // hist of n; re-zeroed in GEMM2 prologue
__device__ unsigned short g_lut[65536];          // n -> quantized gelu (bf16 bits)

__device__ unsigned  g_bins[2048];               // level-0 radix bins (self-rezeroing)
__device__ unsigned  g_bins21[1 << 21];          // low-21-bit histogram (zeroed in GEMM1 prologue)
__device__ unsigned  g_chunk[2048];              // chunk sums for select21
__device__ unsigned  g_prefix;
__device__ long long g_rank;
__device__ float     g_s[2];        // s = 127/amax
__device__ float     g_gamma[2];    // gamma = mean|w| + 1e-5
__device__ float     g_sc1;         // gamma1/s1
__device__ double    g_wpart[2][1024];
__device__ unsigned  g_ctr[8];      // last-block counters (self-resetting)

// ---------------- helpers ----------------
DEV float ff_warp_sum(float v) {
    #pragma unroll
    for (int o = 16; o; o >>= 1) v += __shfl_xor_sync(0xffffffffu, v, o);
    return v;
}
DEV float ff_gelu(float x) {
    return 0.5f * x * (1.0f + erff(x * 0.70710678118654752440f));
}
DEV unsigned ff_pack_bf16(float a, float b) {
    __nv_bfloat162 p = __floats2bfloat162_rn(a, b);
    return *reinterpret_cast<unsigned*>(&p);
}
DEV void ff_cp_async16(void* sdst, const void* gsrc) {
    unsigned d = (unsigned)__cvta_generic_to_shared(sdst);
    asm volatile("cp.async.cg.shared.global [%0], [%1], 16;\n" :: "r"(d), "l"(gsrc));
}
DEV bool ff_last_block_n(int slot, unsigned total) {
    __shared__ bool isLast;
    if (threadIdx.x == 0) {
        __threadfence();
        unsigned v = atomicAdd(&g_ctr[slot], 1u);
        isLast = (v == total - 1);
    }
    __syncthreads();
    return isLast;
}

// parallel bin-select over bins[0..nbins) with 256 threads; nbins multiple of 256
DEV void ff_pselect(const unsigned* bins, int nbins, long long r,
                    int* sel_out, long long* rem_out) {
    __shared__ long long spre[256];
    __shared__ int s_sel;
    __shared__ long long s_rem;
    int t = threadIdx.x;
    int per = nbins >> 8;
    unsigned mysum = 0;
    for (int j = 0; j < per; j++) mysum += bins[t * per + j];
    spre[t] = (long long)mysum;
    __syncthreads();
    #pragma unroll
    for (int off = 1; off < 256; off <<= 1) {
        long long add = (t >= off) ? spre[t - off] : 0;
        __syncthreads();
        spre[t] += add;
        __syncthreads();
    }
    long long incl = spre[t];
    long long excl = incl - (long long)mysum;
    if (r >= excl && r < incl) {
        long long rr = r - excl;
        for (int j = 0; j < per; j++) {
            unsigned c = bins[t * per + j];
            if (rr < (long long)c) { s_sel = t * per + j; s_rem = rr; break; }
            rr -= (long long)c;
        }
    }
    __syncthreads();
    *sel_out = s_sel;
    *rem_out = s_rem;
}

// ---------------- layernorm (one-pass reduction) + fused level-0 histogram ----------------
__global__ __launch_bounds__(256) void ff_ln_kernel(
    const float* __restrict__ x, const float* __restrict__ gam,
    const float* __restrict__ bet)
{
    int row = blockIdx.x;
    int tid = threadIdx.x, w = tid >> 5, l = tid & 31;

    __shared__ unsigned sb[2048];
    for (int i = tid; i < 2048; i += 256) sb[i] = 0u;

    const float4* xr = (const float4*)(x + (size_t)row * DDIM);
    float4 v = xr[tid];

    __shared__ float sh[8], sh2[8];
    __shared__ float s_mu, s_inv;

    float s  = v.x + v.y + v.z + v.w;
    float ss = v.x*v.x + v.y*v.y + v.z*v.z + v.w*v.w;
    float ws  = ff_warp_sum(s);
    float wss = ff_warp_sum(ss);
    if (l == 0) { sh[w] = ws; sh2[w] = wss; }
    __syncthreads();
    if (w == 0) {
        float a = (l < 8) ? sh[l]  : 0.0f;
        float b = (l < 8) ? sh2[l] : 0.0f;
        a = ff_warp_sum(a);
        b = ff_warp_sum(b);
        if (l == 0) {
            float mu = a * (1.0f / DDIM);
            s_mu  = mu;
            s_inv = rsqrtf(b * (1.0f / DDIM) - mu * mu + 1e-5f);
        }
    }
    __syncthreads();
    float mu = s_mu, inv = s_inv;

    float dx = v.x - mu, dy = v.y - mu, dz = v.z - mu, dw = v.w - mu;
    float4 g4 = ((const float4*)gam)[tid], b4 = ((const float4*)bet)[tid];
    float4 o;
    o.x = dx * inv * g4.x + b4.x;
    o.y = dy * inv * g4.y + b4.y;
    o.z = dz * inv * g4.z + b4.z;
    o.w = dw * inv * g4.w + b4.w;
    ((float4*)(g_h1 + (size_t)row * DDIM))[tid] = o;

    atomicAdd(&sb[__float_as_uint(fabsf(o.x)) >> 21], 1u);
    atomicAdd(&sb[__float_as_uint(fabsf(o.y)) >> 21], 1u);
    atomicAdd(&sb[__float_as_uint(fabsf(o.z)) >> 21], 1u);
    atomicAdd(&sb[__float_as_uint(fabsf(o.w)) >> 21], 1u);
    __syncthreads();
    for (int i = tid; i < 2048; i += 256)
        if (sb[i]) atomicAdd(&g_bins[i], sb[i]);
}

// ---------------- both weights: mean|w| + gamma; global last block runs level-0 scan ----------------
__global__ __launch_bounds__(256) void ff_wabs2(const float* __restrict__ w1,
                                                const float* __restrict__ w2)
{
    int half = blockIdx.x >> 10;
    int blk  = blockIdx.x & 1023;
    const float4* p = (const float4*)(half ? w2 : w1) + (size_t)blk * 1024;

    float acc = 0.0f;
    #pragma unroll
    for (int i = 0; i < 4; i++) {
        float4 v = p[threadIdx.x + i * 256];
        acc += fabsf(v.x) + fabsf(v.y) + fabsf(v.z) + fabsf(v.w);
    }
    float ws = ff_warp_sum(acc);
    __shared__ float sw[8];
    int wid = threadIdx.x >> 5, l = threadIdx.x & 31;
    if (l == 0) sw[wid] = ws;
    __syncthreads();
    if (threadIdx.x == 0) {
        double b = 0.0;
        for (int i = 0; i < 8; i++) b += (double)sw[i];
        g_wpart[half][blk] = b;
    }

    if (ff_last_block_n(half, 1024)) {
        if (threadIdx.x == 0) {
            double t = 0.0;
            for (int i = 0; i < 1024; i++) t += g_wpart[half][i];
            g_gamma[half] = (float)(t / (double)NW1) + 1e-5f;
            g_ctr[half] = 0u;
        }
    }

    if (ff_last_block_n(4, 2048)) {
        int sel; long long rem;
        ff_pselect(g_bins, 2048, RANK1, &sel, &rem);
        if (threadIdx.x == 0) {
            g_prefix = (unsigned)sel << 21;
            g_rank   = rem;
            g_ctr[4] = 0u;
        }
        __syncthreads();
        for (int i = threadIdx.x; i < 2048; i += 256) g_bins[i] = 0u;
    }
}

// ---------------- both weights: ternary quantize (bf16) ----------------
__global__ __launch_bounds__(256) void ff_wquant2(const float* __restrict__ w1,
                                                  const float* __restrict__ w2)
{
    int half = blockIdx.x >> 11;
    int blk  = blockIdx.x & 2047;
    float g = g_gamma[half];
    const float4* p = (const float4*)(half ? w2 : w1);
    __nv_bfloat16* out = half ? g_w2q : g_w1q;
    long long n4 = NW1 / 4;
    long long stride = 2048LL * 256;
    for (long long i = (long long)blk * 256 + threadIdx.x; i < n4; i += stride) {
        float4 v = p[i];
        float t0 = fminf(fmaxf(rintf(v.x / g), -1.0f), 1.0f);
        float t1 = fminf(fmaxf(rintf(v.y / g), -1.0f), 1.0f);
        float t2 = fminf(fmaxf(rintf(v.z / g), -1.0f), 1.0f);
        float t3 = fminf(fmaxf(rintf(v.w / g), -1.0f), 1.0f);
        uint2 o;
        o.x = ff_pack_bf16(t0, t1);
        o.y = ff_pack_bf16(t2, t3);
        ((uint2*)out)[i] = o;
    }
}

// ---------------- single-pass low-21-bit histogram of matching elements ----------------
__global__ __launch_bounds__(256) void ff_hist21(long long n4) {
    unsigned pref = g_prefix;              // sel0 << 21
    const float4* p = (const float4*)(const float*)g_h1;
    long long stride = (long long)gridDim.x * blockDim.x;
    long long base = (long long)blockIdx.x * blockDim.x + threadIdx.x;
    for (long long i = base; i < n4; i += 2 * stride) {
        float4 v0 = p[i];
        bool has2 = (i + stride) < n4;
        float4 v1 = has2 ? p[i + stride] : make_float4(-1.f, -1.f, -1.f, -1.f);
        float vv[8] = {v0.x, v0.y, v0.z, v0.w, v1.x, v1.y, v1.z, v1.w};
        int cnt = has2 ? 8 : 4;
        #pragma unroll
        for (int j = 0; j < 8; j++) {
            if (j >= cnt) break;
            unsigned u = __float_as_uint(fabsf(vv[j]));
            if ((u & 0xFFE00000u) == pref)
                atomicAdd(&g_bins21[u & 0x1FFFFFu], 1u);
        }
    }
}

// ---------------- hierarchical select over the 2M-bin histogram (reduction-based) ----------------
__global__ __launch_bounds__(256) void ff_select21() {
    int t = threadIdx.x;
    int chunk = blockIdx.x;               // 2048 blocks, 1024 bins each
    unsigned s = 0;
    #pragma unroll
    for (int j = 0; j < 4; j++) s += g_bins21[(size_t)chunk * 1024 + t * 4 + j];
    __shared__ unsigned red[256];
    red[t] = s;
    __syncthreads();
    for (int o = 128; o; o >>= 1) {
        if (t < o) red[t] += red[t + o];
        __syncthreads();
    }
    if (t == 0) g_chunk[chunk] = red[0];

    if (ff_last_block_n(5, 2048)) {
        int c; long long rr;
        ff_pselect(g_chunk, 2048, g_rank, &c, &rr);
        int b; long long dummy;
        ff_pselect(g_bins21 + (size_t)c * 1024, 1024, rr, &b, &dummy);
        if (t == 0) {
            unsigned bits = g_prefix | (unsigned)(c * 1024 + b);
            float amax = fmaxf(__uint_as_float(bits), 1e-5f);
            g_s[0] = 127.0f / amax;
            g_ctr[5] = 0u;
        }
    }
}

// ---------------- layer-1 activation quantize -> bf16 ints (2x ILP) ----------------
__global__ __launch_bounds__(256) void ff_actquant1(long long n4) {
    float s = g_s[0];
    const float4* in = (const float4*)(const float*)g_h1;
    uint2* out = (uint2*)g_h1q;
    long long stride = (long long)gridDim.x * blockDim.x;
    long long base = (long long)blockIdx.x * blockDim.x + threadIdx.x;
    for (long long i = base; i < n4; i += 2 * stride) {
        float4 v = in[i];
        uint2 o;
        o.x = ff_pack_bf16(fminf(fmaxf(rintf(v.x * s), -128.0f), 127.0f),
                           fminf(fmaxf(rintf(v.y * s), -128.0f), 127.0f));
        o.y = ff_pack_bf16(fminf(fmaxf(rintf(v.z * s), -128.0f), 127.0f),
                           fminf(fmaxf(rintf(v.w * s), -128.0f), 127.0f));
        out[i] = o;
        if (i + stride < n4) {
            float4 u = in[i + stride];
            uint2 o2;
            o2.x = ff_pack_bf16(fminf(fmaxf(rintf(u.x * s), -128.0f), 127.0f),
                                fminf(fmaxf(rintf(u.y * s), -128.0f), 127.0f));
            o2.y = ff_pack_bf16(fminf(fmaxf(rintf(u.z * s), -128.0f), 127.0f),
                                fminf(fmaxf(rintf(u.w * s), -128.0f), 127.0f));
            out[i + stride] = o2;
        }
    }
}

// ---------------- bf16 GEMM: 128x128 tile, K=64/stage, 3 stages, 2 CTA/SM ----------------
// GEMM1 prologue re-zeros g_bins21; GEMM2 prologue re-zeros g_hist2 (both hidden
// under cp.async). GEMM1 epilogue fuses layer-2 histogram + quantile scan.
#define GSTG 32768                 // A 16KB + B 16KB per stage
#define GSMEM (3 * GSTG)           // 96KB dynamic

DEV void ff_load_stage(const __nv_bfloat16* A, const __nv_bfloat16* Bw, int K,
                       int bm, int bn, int kt, unsigned char* sa, int tid)
{
    unsigned char* sb = sa + 16384;
    #pragma unroll
    for (int i = 0; i < 4; i++) {
        int id = tid + i * 256;           // 0..1023
        int row = id >> 3, ch = id & 7;
        int sw = ch ^ (row & 7);
        ff_cp_async16(sa + (row * 8 + sw) * 16, A  + (size_t)(bm + row) * K + kt * 64 + ch * 8);
        ff_cp_async16(sb + (row * 8 + sw) * 16, Bw + (size_t)(bn + row) * K + kt * 64 + ch * 8);
    }
    asm volatile("cp.async.commit_group;\n");
}

template<int LAYER>
__global__ __launch_bounds__(256, 2) void ff_gemm(float* __restrict__ Cext)
{
    constexpr int KD = LAYER ? HDIM : DDIM;
    constexpr int ND = LAYER ? DDIM : HDIM;
    constexpr int KT = KD >> 6;          // K=64 per stage
    const __nv_bfloat16* A  = LAYER ? g_a2q : g_h1q;
    const __nv_bfloat16* Bw = LAYER ? g_w2q : g_w1q;

    extern __shared__ __align__(128) unsigned char smem[];
    const int tid  = threadIdx.x;
    const int lane = tid & 31, warp = tid >> 5;
    const int wm = warp >> 2, wn = warp & 3;     // 2 x 4 warp grid
    const int bm = blockIdx.y * 128, bn = blockIdx.x * 128;   // N on x (L2 reuse)

    float acc[4][4][4];
    #pragma unroll
    for (int a = 0; a < 4; a++)
        #pragma unroll
        for (int b = 0; b < 4; b++)
            #pragma unroll
            for (int c = 0; c < 4; c++) acc[a][b][c] = 0.0f;

    ff_load_stage(A, Bw, KD, bm, bn, 0, smem + 0 * GSTG, tid);
    ff_load_stage(A, Bw, KD, bm, bn, 1, smem + 1 * GSTG, tid);

    if (LAYER == 0) {
        size_t bid = (size_t)blockIdx.y * gridDim.x + blockIdx.x;   // 0..4095
        size_t b0 = bid * 512;
        g_bins21[b0 + tid] = 0u;
        g_bins21[b0 + 256 + tid] = 0u;
    } else {
        size_t bid = (size_t)blockIdx.y * gridDim.x + blockIdx.x;   // 0..1023
        if (tid < 64) g_hist2[bid * 64 + tid] = 0u;
    }

    for (int kt = 0; kt < KT; kt++) {
        if (kt < KT - 1) asm volatile("cp.async.wait_group 1;\n" ::: "memory");
        else             asm volatile("cp.async.wait_group 0;\n" ::: "memory");
        __syncthreads();
        if (kt + 2 < KT)
            ff_load_stage(A, Bw, KD, bm, bn, kt + 2, smem + ((kt + 2) % 3) * GSTG, tid);

        unsigned char* sa = smem + (kt % 3) * GSTG;
        unsigned char* sb = sa + 16384;

        #pragma unroll
        for (int s = 0; s < 4; s++) {             // four k16 steps per K=64 stage
            unsigned ar[4][4];
            #pragma unroll
            for (int mi = 0; mi < 4; mi++) {
                int row = wm * 64 + mi * 16 + ((lane >> 3) & 1) * 8 + (lane & 7);
                int ch  = (2 * s + (lane >> 4)) ^ (row & 7);
                unsigned addr = (unsigned)__cvta_generic_to_shared(sa + (row * 8 + ch) * 16);
                asm volatile("ldmatrix.sync.aligned.m8n8.x4.shared.b16 {%0,%1,%2,%3}, [%4];\n"
                    : "=r"(ar[mi][0]), "=r"(ar[mi][1]), "=r"(ar[mi][2]), "=r"(ar[mi][3])
                    : "r"(addr));
            }
            unsigned br[4][2];
            #pragma unroll
            for (int nj2 = 0; nj2 < 2; nj2++) {
                int row = wn * 32 + nj2 * 16 + ((lane >> 3) & 1) * 8 + (lane & 7);
                int ch  = (2 * s + (lane >> 4)) ^ (row & 7);
                unsigned addr = (unsigned)__cvta_generic_to_shared(sb + (row * 8 + ch) * 16);
                unsigned q0, q1, q2, q3;
                asm volatile("ldmatrix.sync.aligned.m8n8.x4.shared.b16 {%0,%1,%2,%3}, [%4];\n"
                    : "=r"(q0), "=r"(q1), "=r"(q2), "=r"(q3) : "r"(addr));
                br[2 * nj2][0] = q0;     br[2 * nj2][1] = q2;
                br[2 * nj2 + 1][0] = q1; br[2 * nj2 + 1][1] = q3;
            }
            #pragma unroll
            for (int mi = 0; mi < 4; mi++)
                #pragma unroll
                for (int nj = 0; nj < 4; nj++) {
                    asm volatile(
                        "mma.sync.aligned.m16n8k16.row.col.f32.bf16.bf16.f32 "
                        "{%0,%1,%2,%3},{%4,%5,%6,%7},{%8,%9},{%0,%1,%2,%3};\n"
                        : "+f"(acc[mi][nj][0]), "+f"(acc[mi][nj][1]),
                          "+f"(acc[mi][nj][2]), "+f"(acc[mi][nj][3])
                        : "r"(ar[mi][0]), "r"(ar[mi][1]), "r"(ar[mi][2]), "r"(ar[mi][3]),
                          "r"(br[nj][0]), "r"(br[nj][1]));
                }
        }
    }

    if (LAYER == 0) {
        __syncthreads();
        unsigned* hb = (unsigned*)smem;
        for (int i = tid; i < 8192; i += 256) hb[i] = 0u;
        __syncthreads();

        #pragma unroll
        for (int mi = 0; mi < 4; mi++) {
            int r0 = bm + wm * 64 + mi * 16 + (lane >> 2);
            #pragma unroll
            for (int nj = 0; nj < 4; nj++) {
                int cc = bn + wn * 32 + nj * 8 + (lane & 3) * 2;
                int c0 = min(max((int)acc[mi][nj][0], -32768), 32767);
                int c1 = min(max((int)acc[mi][nj][1], -32768), 32767);
                int c2 = min(max((int)acc[mi][nj][2], -32768), 32767);
                int c3 = min(max((int)acc[mi][nj][3], -32768), 32767);
                int b0 = c0 + 4096, b1 = c1 + 4096, b2 = c2 + 4096, b3 = c3 + 4096;
                if ((unsigned)b0 < 8192u) atomicAdd(&hb[b0], 1u); else atomicAdd(&g_hist2[c0 + 32768], 1u);
                if ((unsigned)b1 < 8192u) atomicAdd(&hb[b1], 1u); else atomicAdd(&g_hist2[c1 + 32768], 1u);
                if ((unsigned)b2 < 8192u) atomicAdd(&hb[b2], 1u); else atomicAdd(&g_hist2[c2 + 32768], 1u);
                if ((unsigned)b3 < 8192u) atomicAdd(&hb[b3], 1u); else atomicAdd(&g_hist2[c3 + 32768], 1u);
                *(unsigned*)(g_n2 + (size_t)r0 * ND + cc) =
                    ((unsigned)(unsigned short)(short)c0) | (((unsigned)(unsigned short)(short)c1) << 16);
                *(unsigned*)(g_n2 + (size_t)(r0 + 8) * ND + cc) =
                    ((unsigned)(unsigned short)(short)c2) | (((unsigned)(unsigned short)(short)c3) << 16);
            }
        }
        __syncthreads();
        for (int i = tid; i < 8192; i += 256)
            if (hb[i]) atomicAdd(&g_hist2[i + (32768 - 4096)], hb[i]);

        if (ff_last_block_n(3, gridDim.x * gridDim.y)) {
            long long* partial = (long long*)(smem + 32768);
            int t = tid;
            long long c = 0;
            for (int b = t * 256; b < (t + 1) * 256; b++) c += (long long)g_hist2[b];
            partial[t] = c;
            __syncthreads();
            if (t == 0) {
                double idx = 0.995 * (double)(N2 - 1);
                long long k = (long long)idx;
                double f = idx - (double)k;
                long long cum = 0;
                int chunk = 0;
                for (; chunk < 256; chunk++) {
                    if (cum + partial[chunk] > k) break;
                    cum += partial[chunk];
                }
                long long r = k - cum;
                int nk = 0, nk1 = 0;
                int b = chunk * 256;
                for (;; b++) {
                    long long cc2 = (long long)g_hist2[b];
                    if (r < cc2) {
                        nk = b - 32768;
                        if (r + 1 < cc2) nk1 = nk;
                        else {
                            int b2 = b + 1;
                            while (b2 < 65536 && g_hist2[b2] == 0u) b2++;
                            nk1 = (b2 < 65536) ? (b2 - 32768) : nk;
                        }
                        break;
                    }
                    r -= cc2;
                }
                float sc1 = g_gamma[0] / g_s[0];
                float v0 = ff_gelu(sc1 * (float)nk);
                float v1 = ff_gelu(sc1 * (float)nk1);
                float amax = fmaxf((float)((1.0 - f) * (double)v0 + f * (double)v1), 1e-5f);
                g_s[1] = 127.0f / amax;
                g_sc1 = sc1;
                g_ctr[3] = 0u;
            }
        }
    } else {
        float sc = g_gamma[1] / g_s[1];
        #pragma unroll
        for (int mi = 0; mi < 4; mi++) {
            int r0 = bm + wm * 64 + mi * 16 + (lane >> 2);
            #pragma unroll
            for (int nj = 0; nj < 4; nj++) {
                int cc = bn + wn * 32 + nj * 8 + (lane & 3) * 2;
                float2 p0 = make_float2(acc[mi][nj][0] * sc, acc[mi][nj][1] * sc);
                float2 p1 = make_float2(acc[mi][nj][2] * sc, acc[mi][nj][3] * sc);
                *(float2*)(Cext + (size_t)r0 * ND + cc) = p0;
                *(float2*)(Cext + (size_t)(r0 + 8) * ND + cc) = p1;
            }
        }
    }
}

// ---------------- LUT build ----------------
__global__ void ff_lut_build() {
    int i = blockIdx.x * blockDim.x + threadIdx.x;   // 65536
    int n = i - 32768;
    float g = ff_gelu(g_sc1 * (float)n);
    float q = fminf(fmaxf(rintf(g * g_s[1]), -128.0f), 127.0f);
    __nv_bfloat16 b = __float2bfloat16(q);
    g_lut[i] = *reinterpret_cast<unsigned short*>(&b);
}

// ---------------- layer-2 quantize via LUT gather -> bf16 (2x ILP) ----------------
__global__ __launch_bounds__(256) void ff_actquant2(long long n8) {
    const uint4* in = (const uint4*)g_n2;
    uint4* out = (uint4*)g_a2q;
    const unsigned short* lut = g_lut;
    long long stride = (long long)gridDim.x * blockDim.x;
    long long base = (long long)blockIdx.x * blockDim.x + threadIdx.x;
    for (long long i = base; i < n8; i += 2 * stride) {
        uint4 v0 = in[i];
        unsigned o0[4];
        #pragma unroll
        for (int j = 0; j < 4; j++) {
            unsigned wj = (&v0.x)[j];
            unsigned lo = lut[(wj & 0xffffu) ^ 0x8000u];
            unsigned hi = lut[(wj >> 16) ^ 0x8000u];
            o0[j] = lo | (hi << 16);
        }
        out[i] = make_uint4(o0[0], o0[1], o0[2], o0[3]);
        if (i + stride < n8) {
            uint4 v1 = in[i + stride];
            unsigned o1[4];
            #pragma unroll
            for (int j = 0; j < 4; j++) {
                unsigned wj = (&v1.x)[j];
                unsigned lo = lut[(wj & 0xffffu) ^ 0x8000u];
                unsigned hi = lut[(wj >> 16) ^ 0x8000u];
                o1[j] = lo | (hi << 16);
            }
            out[i + stride] = make_uint4(o1[0], o1[1], o1[2], o1[3]);
        }
    }
}

// ---------------- launch ----------------
extern "C" void kernel_launch(void* const* d_in, const int* in_sizes, int n_in,
                              void* d_out, int out_size)
{
    const float* x    = (const float*)d_in[0];
    const float* ln_g = (const float*)d_in[1];
    const float* ln_b = (const float*)d_in[2];
    const float* w1   = (const float*)d_in[3];
    const float* w2   = (const float*)d_in[4];
    float* out = (float*)d_out;

    cudaFuncSetAttribute(ff_gemm<0>, cudaFuncAttributeMaxDynamicSharedMemorySize, GSMEM);
    cudaFuncSetAttribute(ff_gemm<1>, cudaFuncAttributeMaxDynamicSharedMemorySize, GSMEM);

    // LayerNorm (one-pass reduction, fused level-0 histogram)
    ff_ln_kernel<<<MM, 256>>>(x, ln_g, ln_b);

    // Weight gammas (+ fused level-0 scan in global last block), then quantize
    ff_wabs2<<<2048, 256>>>(w1, w2);
    ff_wquant2<<<4096, 256>>>(w1, w2);

    // Layer-1 quantile: single-pass 21-bit histogram + hierarchical select (exact)
    ff_hist21<<<2048, 256>>>(N1 / 4);
    ff_select21<<<2048, 256>>>();

    // Quantize acts #1 -> bf16 ints
    ff_actquant1<<<4096, 256>>>(N1 / 4);

    // GEMM1 (prologue rezeros bins21; epilogue: layer-2 histogram + quantile)
    ff_gemm<0><<<dim3(HDIM / 128, MM / 128), 256, GSMEM>>>(nullptr);

    // LUT build
    ff_lut_build<<<256, 256>>>();

    // GELU + quantize acts #2 via LUT -> bf16 ints
    ff_actquant2<<<8192, 256>>>(N2 / 8);

    // GEMM2 (prologue rezeros hist2) -> fp32 output
    ff_gemm<1><<<dim3(DDIM / 128, MM / 128), 256, GSMEM>>>(out);
}